// round 9
// baseline (speedup 1.0000x reference)
#include <cuda_runtime.h>

#define NN 100000
#define EE 1600000
#define DD 64
#define GG 64
#define OUTC 10
#define NB ((NN + 255) / 256)   // 391 scan blocks

// ---- scratch ----
__device__ int    g_is64;
__device__ int    g_batch[NN];
__device__ int    g_deg[NN];
__device__ int    g_cursor[NN];
__device__ int    g_rowstart[NN];     // block-local exclusive prefix
__device__ int    g_bsum[NB];
__device__ int    g_bsum_sc[NB];      // exclusive scan of block sums
__device__ int    g_adj[EE];
__device__ float4 g_h0[(size_t)NN * (DD / 4)];
__device__ float4 g_h1[(size_t)NN * (DD / 4)];
__device__ float  g_pool[GG * DD];

__device__ __forceinline__ int load_idx(const void* p, size_t i, int is64) {
    return is64 ? (int)((const long long*)p)[i] : ((const int*)p)[i];
}

// detect dtype per block (reads same head lines -> broadcast), convert batch,
// zero deg/cursor. Block 0 thread 0 publishes g_is64 for later kernels.
__global__ void prep_kernel(const void* __restrict__ ei,
                            const void* __restrict__ bat) {
    __shared__ int s_is64;
    if (threadIdx.x == 0) {
        const unsigned int* w = (const unsigned int*)ei;
        int is64 = 1;
        for (int i = 0; i < 16; i++)
            if (w[2 * i + 1] != 0u) { is64 = 0; break; }
        s_is64 = is64;
        if (blockIdx.x == 0) g_is64 = is64;
    }
    __syncthreads();
    int i = blockIdx.x * blockDim.x + threadIdx.x;
    if (i < NN) {
        g_batch[i]  = load_idx(bat, i, s_is64);
        g_deg[i]    = 0;
        g_cursor[i] = 0;
    }
}

__global__ void deg_kernel(const void* __restrict__ ei) {
    int e = blockIdx.x * blockDim.x + threadIdx.x;
    if (e < EE) atomicAdd(&g_deg[load_idx(ei, (size_t)EE + e, g_is64)], 1);
}

__global__ void scan_block_kernel() {
    __shared__ int s[256];
    int tid = threadIdx.x;
    int i = blockIdx.x * 256 + tid;
    int v = (i < NN) ? g_deg[i] : 0;
    s[tid] = v;
    __syncthreads();
    #pragma unroll
    for (int off = 1; off < 256; off <<= 1) {
        int t = (tid >= off) ? s[tid - off] : 0;
        __syncthreads();
        s[tid] += t;
        __syncthreads();
    }
    if (i < NN) g_rowstart[i] = s[tid] - v;     // local exclusive
    if (tid == 255) g_bsum[blockIdx.x] = s[255];
}

__global__ void scan_top_kernel() {
    __shared__ int s[512];
    int tid = threadIdx.x;
    int v = (tid < NB) ? g_bsum[tid] : 0;
    s[tid] = v;
    __syncthreads();
    #pragma unroll
    for (int off = 1; off < 512; off <<= 1) {
        int t = (tid >= off) ? s[tid - off] : 0;
        __syncthreads();
        s[tid] += t;
        __syncthreads();
    }
    if (tid < NB) g_bsum_sc[tid] = s[tid] - v;
}

__global__ void csr_fill_kernel(const void* __restrict__ ei) {
    int e = blockIdx.x * blockDim.x + threadIdx.x;
    if (e < EE) {
        int is64 = g_is64;
        int src = load_idx(ei, e, is64);
        int dst = load_idx(ei, (size_t)EE + e, is64);
        int pos = atomicAdd(&g_cursor[dst], 1);
        g_adj[g_rowstart[dst] + g_bsum_sc[dst >> 8] + pos] = src;
    }
}

// ---------------- fused SAGE layer ----------------
// Phase 1: warp-per-node gather-mean directly into transposed smem tile sA.
// Phase 2: register-tiled GEMM (16x16 threads, 4x4 tile) pass0 agg@Wl.
// Phase 3: restage sA = own h rows (transposed), sW = Wr; pass1 += h@Wr.
// Epilogue: +bias, relu, float4 store. L2-bound gather of one block overlaps
// FMA-bound GEMM of co-resident blocks.
__global__ void sage_kernel(int sel, const float* __restrict__ x,
                            const float* __restrict__ Wl,
                            const float* __restrict__ bl,
                            const float* __restrict__ Wr) {
    __shared__ __align__(16) float sA[DD][68];
    __shared__ __align__(16) float sW[DD][DD];
    __shared__ float sb[DD];

    const float* hin  = (sel == 0) ? x
                       : (sel == 1) ? (const float*)g_h0 : (const float*)g_h1;
    float*       hout = (sel == 0) ? (float*)g_h0
                       : (sel == 1) ? (float*)g_h1 : (float*)g_h0;

    int tid  = threadIdx.x;
    int base = blockIdx.x * 64;
    int lane = tid & 31;
    int w    = tid >> 5;          // warp 0..7
    if (tid < DD) sb[tid] = bl[tid];

    // stage Wl
    for (int i = tid; i < DD * DD; i += 256) sW[i >> 6][i & 63] = Wl[i];

    // phase 1: gather-mean, 8 nodes per warp, lane owns dims {2L, 2L+1}
    const float2* hin2 = (const float2*)hin;
    #pragma unroll
    for (int i = 0; i < 8; i++) {
        int nr = w * 8 + i;
        int node = base + nr;
        float ax = 0.f, ay = 0.f;
        float inv = 0.f;
        if (node < NN) {
            int rs = g_rowstart[node] + g_bsum_sc[node >> 8];
            int re = (node + 1 < NN)
                   ? g_rowstart[node + 1] + g_bsum_sc[(node + 1) >> 8] : EE;
            int e = rs;
            for (; e + 8 <= re; e += 8) {
                int s0 = g_adj[e+0], s1 = g_adj[e+1], s2 = g_adj[e+2], s3 = g_adj[e+3];
                int s4 = g_adj[e+4], s5 = g_adj[e+5], s6 = g_adj[e+6], s7 = g_adj[e+7];
                float2 v0 = hin2[(size_t)s0 * 32 + lane];
                float2 v1 = hin2[(size_t)s1 * 32 + lane];
                float2 v2 = hin2[(size_t)s2 * 32 + lane];
                float2 v3 = hin2[(size_t)s3 * 32 + lane];
                float2 v4 = hin2[(size_t)s4 * 32 + lane];
                float2 v5 = hin2[(size_t)s5 * 32 + lane];
                float2 v6 = hin2[(size_t)s6 * 32 + lane];
                float2 v7 = hin2[(size_t)s7 * 32 + lane];
                ax += (v0.x + v1.x) + (v2.x + v3.x) + ((v4.x + v5.x) + (v6.x + v7.x));
                ay += (v0.y + v1.y) + (v2.y + v3.y) + ((v4.y + v5.y) + (v6.y + v7.y));
            }
            for (; e < re; e++) {
                int s = g_adj[e];
                float2 v = hin2[(size_t)s * 32 + lane];
                ax += v.x; ay += v.y;
            }
            inv = 1.0f / (float)max(re - rs, 1);
        }
        sA[2 * lane + 0][nr] = ax * inv;
        sA[2 * lane + 1][nr] = ay * inv;
    }
    __syncthreads();

    // phase 2: GEMM pass 0 (agg @ Wl)
    int tc = tid & 15;
    int tr = tid >> 4;
    float acc[4][4];
    #pragma unroll
    for (int i = 0; i < 4; i++)
        #pragma unroll
        for (int j = 0; j < 4; j++) acc[i][j] = 0.f;

    #pragma unroll 8
    for (int k = 0; k < DD; k++) {
        float4 a4 = *(const float4*)&sA[k][tr * 4];
        float4 w4 = *(const float4*)&sW[k][tc * 4];
        float av[4] = { a4.x, a4.y, a4.z, a4.w };
        float wv[4] = { w4.x, w4.y, w4.z, w4.w };
        #pragma unroll
        for (int i = 0; i < 4; i++)
            #pragma unroll
            for (int j = 0; j < 4; j++)
                acc[i][j] = fmaf(av[i], wv[j], acc[i][j]);
    }
    __syncthreads();

    // phase 3: restage sW = Wr, sA = own h rows transposed
    for (int i = tid; i < DD * DD; i += 256) sW[i >> 6][i & 63] = Wr[i];
    {
        int r_st   = tid >> 2;
        int row_st = base + r_st;
        int k4b    = (tid & 3) * 4;
        #pragma unroll
        for (int j = 0; j < 4; j++) {
            int k4 = k4b + j;
            float4 v = make_float4(0.f, 0.f, 0.f, 0.f);
            if (row_st < NN) v = ((const float4*)hin)[(size_t)row_st * (DD/4) + k4];
            sA[k4 * 4 + 0][r_st] = v.x;
            sA[k4 * 4 + 1][r_st] = v.y;
            sA[k4 * 4 + 2][r_st] = v.z;
            sA[k4 * 4 + 3][r_st] = v.w;
        }
    }
    __syncthreads();

    // GEMM pass 1 (h @ Wr)
    #pragma unroll 8
    for (int k = 0; k < DD; k++) {
        float4 a4 = *(const float4*)&sA[k][tr * 4];
        float4 w4 = *(const float4*)&sW[k][tc * 4];
        float av[4] = { a4.x, a4.y, a4.z, a4.w };
        float wv[4] = { w4.x, w4.y, w4.z, w4.w };
        #pragma unroll
        for (int i = 0; i < 4; i++)
            #pragma unroll
            for (int j = 0; j < 4; j++)
                acc[i][j] = fmaf(av[i], wv[j], acc[i][j]);
    }

    // epilogue
    #pragma unroll
    for (int i = 0; i < 4; i++) {
        int row = base + tr * 4 + i;
        if (row < NN) {
            float4 o;
            o.x = fmaxf(acc[i][0] + sb[tc * 4 + 0], 0.f);
            o.y = fmaxf(acc[i][1] + sb[tc * 4 + 1], 0.f);
            o.z = fmaxf(acc[i][2] + sb[tc * 4 + 2], 0.f);
            o.w = fmaxf(acc[i][3] + sb[tc * 4 + 3], 0.f);
            *(float4*)&hout[(size_t)row * DD + tc * 4] = o;
        }
    }
}

// ---------------- global mean pool (batch sorted -> binary search) ----------
__global__ void pool_kernel() {
    int g = blockIdx.x;
    int col = threadIdx.x;
    int a = 0, b = NN;
    while (a < b) { int m = (a + b) >> 1; if (g_batch[m] < g) a = m + 1; else b = m; }
    int start = a;
    b = NN;
    while (a < b) { int m = (a + b) >> 1; if (g_batch[m] < g + 1) a = m + 1; else b = m; }
    int end = a;
    float acc = 0.f;
    const float* h = (const float*)g_h0;
    for (int n = start; n < end; n++) acc += h[(size_t)n * DD + col];
    g_pool[g * DD + col] = acc / fmaxf((float)(end - start), 1.f);
}

// ---------------- final MLP ----------------
__global__ void mlp_kernel(const float* __restrict__ l0W,
                           const float* __restrict__ l0b,
                           const float* __restrict__ outW,
                           const float* __restrict__ outb,
                           float* __restrict__ out) {
    __shared__ float sg[DD];
    __shared__ float sh[DD];
    int gi = blockIdx.x, t = threadIdx.x;
    sg[t] = g_pool[gi * DD + t];
    __syncthreads();
    float acc = l0b[t];
    #pragma unroll
    for (int k = 0; k < DD; k++) acc = fmaf(sg[k], l0W[k * DD + t], acc);
    sh[t] = fmaxf(acc, 0.f);
    __syncthreads();
    if (t < OUTC) {
        float a = outb[t];
        #pragma unroll
        for (int k = 0; k < DD; k++) a = fmaf(sh[k], outW[k * OUTC + t], a);
        out[gi * OUTC + t] = a;
    }
}

extern "C" void kernel_launch(void* const* d_in, const int* in_sizes, int n_in,
                              void* d_out, int out_size) {
    const float* x    = (const float*)d_in[0];
    const void*  ei   = d_in[1];
    const void*  bat  = d_in[2];
    const float* c_Wl[3] = { (const float*)d_in[3], (const float*)d_in[6], (const float*)d_in[9]  };
    const float* c_bl[3] = { (const float*)d_in[4], (const float*)d_in[7], (const float*)d_in[10] };
    const float* c_Wr[3] = { (const float*)d_in[5], (const float*)d_in[8], (const float*)d_in[11] };
    const float* l0W  = (const float*)d_in[12];
    const float* l0b  = (const float*)d_in[13];
    const float* outW = (const float*)d_in[14];
    const float* outb = (const float*)d_in[15];
    float* out = (float*)d_out;

    // CSR build: 5 launches (so ncu -s 5 captures sage layer 0)
    prep_kernel<<<NB, 256>>>(ei, bat);
    deg_kernel<<<(EE + 255) / 256, 256>>>(ei);
    scan_block_kernel<<<NB, 256>>>();
    scan_top_kernel<<<1, 512>>>();
    csr_fill_kernel<<<(EE + 255) / 256, 256>>>(ei);

    // 3 fused SAGE layers
    const int sage_blocks = (NN + 63) / 64;
    for (int l = 0; l < 3; l++)
        sage_kernel<<<sage_blocks, 256>>>(l, x, c_Wl[l], c_bl[l], c_Wr[l]);

    // pooling + MLP
    pool_kernel<<<GG, DD>>>();
    mlp_kernel<<<GG, DD>>>(l0W, l0b, outW, outb, out);
}

// round 10
// speedup vs baseline: 1.0683x; 1.0683x over previous
#include <cuda_runtime.h>

#define NN 100000
#define EE 1600000
#define DD 64
#define GG 64
#define OUTC 10
#define NB ((NN + 255) / 256)   // 391 scan blocks

// ---- scratch ----
__device__ int    g_is64;
__device__ int    g_batch[NN];
__device__ int    g_deg[NN];      // zeroed by trailing fold (and module load)
__device__ int    g_cursor[NN];   // zeroed by trailing fold (and module load)
__device__ int    g_rowstart[NN]; // block-local exclusive prefix
__device__ int    g_bsum[NB];
__device__ int    g_bsum_sc[NB];
__device__ int    g_adj[EE];
__device__ float4 g_agg[(size_t)NN * (DD / 4)];
__device__ float4 g_h0 [(size_t)NN * (DD / 4)];
__device__ float4 g_h1 [(size_t)NN * (DD / 4)];
__device__ float  g_pool[GG * DD];

__device__ __forceinline__ int load_idx(const void* p, size_t i, int is64) {
    return is64 ? (int)((const long long*)p)[i] : ((const int*)p)[i];
}

// ---- launch 1: dtype detect + batch convert + degree histogram -------------
// g_deg/g_cursor arrive zeroed (module load on first call; trailing fold after).
__global__ void prep_deg_kernel(const void* __restrict__ ei,
                                const void* __restrict__ bat) {
    __shared__ int s_is64;
    if (threadIdx.x == 0) {
        const unsigned int* w = (const unsigned int*)ei;
        int is64 = 1;
        for (int i = 0; i < 16; i++)
            if (w[2 * i + 1] != 0u) { is64 = 0; break; }
        s_is64 = is64;
        if (blockIdx.x == 0) g_is64 = is64;
    }
    __syncthreads();
    int is64 = s_is64;
    int e = blockIdx.x * blockDim.x + threadIdx.x;
    if (e < NN) g_batch[e] = load_idx(bat, e, is64);
    if (e < EE) atomicAdd(&g_deg[load_idx(ei, (size_t)EE + e, is64)], 1);
}

// ---- launch 2: block-local exclusive scan ----------------------------------
__global__ void scan_block_kernel() {
    __shared__ int s[256];
    int tid = threadIdx.x;
    int i = blockIdx.x * 256 + tid;
    int v = (i < NN) ? g_deg[i] : 0;
    s[tid] = v;
    __syncthreads();
    #pragma unroll
    for (int off = 1; off < 256; off <<= 1) {
        int t = (tid >= off) ? s[tid - off] : 0;
        __syncthreads();
        s[tid] += t;
        __syncthreads();
    }
    if (i < NN) g_rowstart[i] = s[tid] - v;     // local exclusive
    if (tid == 255) g_bsum[blockIdx.x] = s[255];
}

// ---- launch 3: scan the 391 block sums -------------------------------------
__global__ void scan_top_kernel() {
    __shared__ int s[512];
    int tid = threadIdx.x;
    int v = (tid < NB) ? g_bsum[tid] : 0;
    s[tid] = v;
    __syncthreads();
    #pragma unroll
    for (int off = 1; off < 512; off <<= 1) {
        int t = (tid >= off) ? s[tid - off] : 0;
        __syncthreads();
        s[tid] += t;
        __syncthreads();
    }
    if (tid < NB) g_bsum_sc[tid] = s[tid] - v;
}

// ---- launch 4 (profiled): adjacency fill -----------------------------------
__global__ void csr_fill_kernel(const void* __restrict__ ei) {
    int e = blockIdx.x * blockDim.x + threadIdx.x;
    if (e < EE) {
        int is64 = g_is64;
        int src = load_idx(ei, e, is64);
        int dst = load_idx(ei, (size_t)EE + e, is64);
        int pos = atomicAdd(&g_cursor[dst], 1);
        g_adj[g_rowstart[dst] + g_bsum_sc[dst >> 8] + pos] = src;
    }
}

// ---- gather-mean: one warp per node, lane owns float2, unroll x8 (MLP 8) ---
__global__ void gather_kernel(int sel, const float* __restrict__ x) {
    int gtid = blockIdx.x * blockDim.x + threadIdx.x;
    int node = gtid >> 5;
    if (node >= NN) return;
    int lane = threadIdx.x & 31;

    const float2* hin = (sel == 0) ? (const float2*)x
                       : (sel == 1) ? (const float2*)g_h0 : (const float2*)g_h1;

    int rs = g_rowstart[node] + g_bsum_sc[node >> 8];
    int re = (node + 1 < NN)
           ? g_rowstart[node + 1] + g_bsum_sc[(node + 1) >> 8] : EE;
    float ax = 0.f, ay = 0.f;
    int e = rs;
    for (; e + 8 <= re; e += 8) {
        int s0 = g_adj[e+0], s1 = g_adj[e+1], s2 = g_adj[e+2], s3 = g_adj[e+3];
        int s4 = g_adj[e+4], s5 = g_adj[e+5], s6 = g_adj[e+6], s7 = g_adj[e+7];
        float2 v0 = hin[(size_t)s0 * 32 + lane];
        float2 v1 = hin[(size_t)s1 * 32 + lane];
        float2 v2 = hin[(size_t)s2 * 32 + lane];
        float2 v3 = hin[(size_t)s3 * 32 + lane];
        float2 v4 = hin[(size_t)s4 * 32 + lane];
        float2 v5 = hin[(size_t)s5 * 32 + lane];
        float2 v6 = hin[(size_t)s6 * 32 + lane];
        float2 v7 = hin[(size_t)s7 * 32 + lane];
        ax += (v0.x + v1.x) + (v2.x + v3.x) + ((v4.x + v5.x) + (v6.x + v7.x));
        ay += (v0.y + v1.y) + (v2.y + v3.y) + ((v4.y + v5.y) + (v6.y + v7.y));
    }
    for (; e < re; e++) {
        int s = g_adj[e];
        float2 v = hin[(size_t)s * 32 + lane];
        ax += v.x; ay += v.y;
    }
    float inv = 1.0f / (float)max(re - rs, 1);
    ((float2*)g_agg)[(size_t)node * 32 + lane] = make_float2(ax * inv, ay * inv);
}

// ---- register-tiled linear: out = relu([agg|h]@[Wl;Wr] + bl) ---------------
// 256 threads = 16x16, 4x4 register tile each; 1 LDS.128 pair per 16 FMAs.
// sel==2 additionally re-zeros g_deg/g_cursor for the next call/replay.
__global__ void linear_kernel(int sel, const float* __restrict__ x,
                              const float* __restrict__ Wl,
                              const float* __restrict__ bl,
                              const float* __restrict__ Wr) {
    __shared__ __align__(16) float sA[DD][68];
    __shared__ __align__(16) float sW[DD][DD];
    __shared__ float sb[DD];

    const float* hin  = (sel == 0) ? x
                       : (sel == 1) ? (const float*)g_h0 : (const float*)g_h1;
    float*       hout = (sel == 0) ? (float*)g_h0
                       : (sel == 1) ? (float*)g_h1 : (float*)g_h0;

    int tid  = threadIdx.x;
    int base = blockIdx.x * 64;
    int tc = tid & 15;
    int tr = tid >> 4;
    if (tid < DD) sb[tid] = bl[tid];

    if (sel == 2 && tid < 64) {         // trailing state-reset fold
        int n = base + tid;
        if (n < NN) { g_deg[n] = 0; g_cursor[n] = 0; }
    }

    float acc[4][4];
    #pragma unroll
    for (int i = 0; i < 4; i++)
        #pragma unroll
        for (int j = 0; j < 4; j++) acc[i][j] = 0.f;

    int r_st   = tid >> 2;
    int row_st = base + r_st;
    int k4b    = (tid & 3) * 4;

    #pragma unroll
    for (int pass = 0; pass < 2; pass++) {
        const float* A = (pass == 0) ? (const float*)g_agg : hin;
        const float* W = (pass == 0) ? Wl : Wr;
        for (int i = tid; i < DD * DD; i += 256) sW[i >> 6][i & 63] = W[i];
        #pragma unroll
        for (int j = 0; j < 4; j++) {
            int k4 = k4b + j;
            float4 v = make_float4(0.f, 0.f, 0.f, 0.f);
            if (row_st < NN) v = ((const float4*)A)[(size_t)row_st * (DD/4) + k4];
            sA[k4 * 4 + 0][r_st] = v.x;
            sA[k4 * 4 + 1][r_st] = v.y;
            sA[k4 * 4 + 2][r_st] = v.z;
            sA[k4 * 4 + 3][r_st] = v.w;
        }
        __syncthreads();
        #pragma unroll 8
        for (int k = 0; k < DD; k++) {
            float4 a4 = *(const float4*)&sA[k][tr * 4];
            float4 w4 = *(const float4*)&sW[k][tc * 4];
            float av[4] = { a4.x, a4.y, a4.z, a4.w };
            float wv[4] = { w4.x, w4.y, w4.z, w4.w };
            #pragma unroll
            for (int i = 0; i < 4; i++)
                #pragma unroll
                for (int j = 0; j < 4; j++)
                    acc[i][j] = fmaf(av[i], wv[j], acc[i][j]);
        }
        __syncthreads();
    }

    #pragma unroll
    for (int i = 0; i < 4; i++) {
        int row = base + tr * 4 + i;
        if (row < NN) {
            float4 o;
            o.x = fmaxf(acc[i][0] + sb[tc * 4 + 0], 0.f);
            o.y = fmaxf(acc[i][1] + sb[tc * 4 + 1], 0.f);
            o.z = fmaxf(acc[i][2] + sb[tc * 4 + 2], 0.f);
            o.w = fmaxf(acc[i][3] + sb[tc * 4 + 3], 0.f);
            *(float4*)&hout[(size_t)row * DD + tc * 4] = o;
        }
    }
}

// ---- global mean pool (batch sorted -> binary search) ----------------------
__global__ void pool_kernel() {
    int g = blockIdx.x;
    int col = threadIdx.x;
    int a = 0, b = NN;
    while (a < b) { int m = (a + b) >> 1; if (g_batch[m] < g) a = m + 1; else b = m; }
    int start = a;
    b = NN;
    while (a < b) { int m = (a + b) >> 1; if (g_batch[m] < g + 1) a = m + 1; else b = m; }
    int end = a;
    float acc = 0.f;
    const float* h = (const float*)g_h0;
    for (int n = start; n < end; n++) acc += h[(size_t)n * DD + col];
    g_pool[g * DD + col] = acc / fmaxf((float)(end - start), 1.f);
}

// ---- final MLP -------------------------------------------------------------
__global__ void mlp_kernel(const float* __restrict__ l0W,
                           const float* __restrict__ l0b,
                           const float* __restrict__ outW,
                           const float* __restrict__ outb,
                           float* __restrict__ out) {
    __shared__ float sg[DD];
    __shared__ float sh[DD];
    int gi = blockIdx.x, t = threadIdx.x;
    sg[t] = g_pool[gi * DD + t];
    __syncthreads();
    float acc = l0b[t];
    #pragma unroll
    for (int k = 0; k < DD; k++) acc = fmaf(sg[k], l0W[k * DD + t], acc);
    sh[t] = fmaxf(acc, 0.f);
    __syncthreads();
    if (t < OUTC) {
        float a = outb[t];
        #pragma unroll
        for (int k = 0; k < DD; k++) a = fmaf(sh[k], outW[k * OUTC + t], a);
        out[gi * OUTC + t] = a;
    }
}

extern "C" void kernel_launch(void* const* d_in, const int* in_sizes, int n_in,
                              void* d_out, int out_size) {
    const float* x    = (const float*)d_in[0];
    const void*  ei   = d_in[1];
    const void*  bat  = d_in[2];
    const float* c_Wl[3] = { (const float*)d_in[3], (const float*)d_in[6], (const float*)d_in[9]  };
    const float* c_bl[3] = { (const float*)d_in[4], (const float*)d_in[7], (const float*)d_in[10] };
    const float* c_Wr[3] = { (const float*)d_in[5], (const float*)d_in[8], (const float*)d_in[11] };
    const float* l0W  = (const float*)d_in[12];
    const float* l0b  = (const float*)d_in[13];
    const float* outW = (const float*)d_in[14];
    const float* outb = (const float*)d_in[15];
    float* out = (float*)d_out;

    // CSR build (csr_fill is the 4th launch -> gets profiled)
    prep_deg_kernel<<<(EE + 255) / 256, 256>>>(ei, bat);
    scan_block_kernel<<<NB, 256>>>();
    scan_top_kernel<<<1, 512>>>();
    csr_fill_kernel<<<(EE + 255) / 256, 256>>>(ei);

    // 3 SAGE layers: gather-mean then register-tiled linear
    const int gather_blocks = (NN * 32 + 255) / 256;
    const int linear_blocks = (NN + 63) / 64;
    for (int l = 0; l < 3; l++) {
        gather_kernel<<<gather_blocks, 256>>>(l, x);
        linear_kernel<<<linear_blocks, 256>>>(l, x, c_Wl[l], c_bl[l], c_Wr[l]);
    }

    // pooling + MLP
    pool_kernel<<<GG, DD>>>();
    mlp_kernel<<<GG, DD>>>(l0W, l0b, outW, outb, out);
}